// round 11
// baseline (speedup 1.0000x reference)
#include <cuda_runtime.h>
#include <mma.h>
#include <cstddef>

using namespace nvcuda;

#define N_NODESC 100000
#define N_EDGESC 1600000
#define NFEAT 7
#define HID 128
#define NCLASS 5
#define NGRAPHS 8

// ---------------- scratch (device globals; no allocation allowed) ----------
__device__ __align__(16) float g_agg[N_NODESC * HID];
__device__ __align__(16) float g_h0[N_NODESC * HID];
__device__ __align__(16) float g_h1[N_NODESC * HID];
__device__ float g_pool[NGRAPHS * HID];
__device__ float g_cnt[NGRAPHS];
// CSR-by-destination scratch
__device__ int g_deg[N_NODESC];
__device__ int g_off[N_NODESC + 1];
__device__ int g_cur[N_NODESC];
__device__ int g_bsum[128];
__device__ int g_perm[N_EDGESC];
// edge data pre-permuted into CSR order
__device__ int g_srcs[N_EDGESC];
__device__ float g_eas[N_EDGESC];

// ================= CSR build ===============================================
__global__ void hist_kernel(const int* __restrict__ dst, int* __restrict__ deg) {
    int e = blockIdx.x * blockDim.x + threadIdx.x;
    if (e < N_EDGESC) atomicAdd(&deg[dst[e]], 1);
}

#define SCAN_T 256
#define SCAN_E 1024
#define SCAN_NB ((N_NODESC + SCAN_E - 1) / SCAN_E)   // 98

__global__ void scan_local(const int* __restrict__ deg, int* __restrict__ off,
                           int* __restrict__ bsum) {
    __shared__ int tsum[SCAN_T];
    int b = blockIdx.x, t = threadIdx.x;
    int base = b * SCAN_E + t * 4;
    int v[4], ex[4];
    int run = 0;
#pragma unroll
    for (int j = 0; j < 4; j++) {
        int idx = base + j;
        v[j] = (idx < N_NODESC) ? deg[idx] : 0;
        ex[j] = run;
        run += v[j];
    }
    tsum[t] = run;
    __syncthreads();
    for (int ofs = 1; ofs < SCAN_T; ofs <<= 1) {
        int val = (t >= ofs) ? tsum[t - ofs] : 0;
        __syncthreads();
        tsum[t] += val;
        __syncthreads();
    }
    int texc = tsum[t] - run;
#pragma unroll
    for (int j = 0; j < 4; j++) {
        int idx = base + j;
        if (idx < N_NODESC) off[idx] = texc + ex[j];
    }
    if (t == SCAN_T - 1) bsum[b] = tsum[t];
}

__global__ void scan_sums(int* __restrict__ bsum) {
    if (threadIdx.x == 0) {
        int run = 0;
        for (int b = 0; b < SCAN_NB; b++) {
            int t = bsum[b];
            bsum[b] = run;
            run += t;
        }
    }
}

__global__ void scan_add(int* __restrict__ off, const int* __restrict__ bsum) {
    int b = blockIdx.x, t = threadIdx.x;
    int add = bsum[b];
    int base = b * SCAN_E + t * 4;
#pragma unroll
    for (int j = 0; j < 4; j++) {
        int idx = base + j;
        if (idx < N_NODESC) off[idx] += add;
    }
    if (b == 0 && t == 0) off[N_NODESC] = N_EDGESC;
}

__global__ void fill_kernel(const int* __restrict__ dst, int* __restrict__ cur,
                            int* __restrict__ perm) {
    int e = blockIdx.x * blockDim.x + threadIdx.x;
    if (e < N_EDGESC) {
        int p = atomicAdd(&cur[dst[e]], 1);
        perm[p] = e;
    }
}

__global__ void permute_edges(const int* __restrict__ perm,
                              const int* __restrict__ src,
                              const float* __restrict__ ea,
                              int* __restrict__ srcs,
                              float* __restrict__ eas) {
    int i = blockIdx.x * blockDim.x + threadIdx.x;
    if (i < N_EDGESC) {
        int e = perm[i];
        srcs[i] = __ldg(&src[e]);
        eas[i] = __ldg(&ea[e]);
    }
}

// ================= layer 1: in = 7, gather by destination ==================
__global__ void __launch_bounds__(256)
gather7(const float* __restrict__ x, const int* __restrict__ srcs,
        const float* __restrict__ eas, const int* __restrict__ off,
        const float* __restrict__ We, const float* __restrict__ be,
        float* __restrict__ agg7) {
    int n = (blockIdx.x * blockDim.x + threadIdx.x) >> 5;
    int lane = threadIdx.x & 31;
    if (n >= N_NODESC) return;
    float w[NFEAT], bb[NFEAT];
#pragma unroll
    for (int j = 0; j < NFEAT; j++) { w[j] = __ldg(&We[j]); bb[j] = __ldg(&be[j]); }
    int i0 = __ldg(&off[n]), i1 = __ldg(&off[n + 1]);
    float acc[NFEAT];
#pragma unroll
    for (int j = 0; j < NFEAT; j++) acc[j] = 0.0f;
    for (int i = i0 + lane; i < i1; i += 32) {
        int s = __ldg(&srcs[i]);
        float a = __ldg(&eas[i]);
#pragma unroll
        for (int j = 0; j < NFEAT; j++)
            acc[j] += fmaxf(fmaf(a, w[j], bb[j]) + __ldg(&x[s * NFEAT + j]), 0.0f);
    }
#pragma unroll
    for (int o = 16; o > 0; o >>= 1)
#pragma unroll
        for (int j = 0; j < NFEAT; j++)
            acc[j] += __shfl_down_sync(0xffffffffu, acc[j], o);
    if (lane == 0) {
#pragma unroll
        for (int j = 0; j < NFEAT; j++) agg7[n * NFEAT + j] = acc[j];
    }
}

// ---------------- layer 1 gemm: [N,7] @ [7,128], relu ---------------------
#define GM1 32
__global__ void gemm7(const float* __restrict__ agg, const float* __restrict__ x,
                      const float* __restrict__ W, const float* __restrict__ b,
                      float* __restrict__ out) {
    __shared__ float Ws[NFEAT * HID];
    __shared__ float bs[HID];
    int j = threadIdx.x;  // 128 threads
#pragma unroll
    for (int k = 0; k < NFEAT; k++) Ws[k * HID + j] = W[k * HID + j];
    bs[j] = b[j];
    __syncthreads();
    int row0 = blockIdx.x * GM1;
    for (int r = 0; r < GM1; r++) {
        int row = row0 + r;
        if (row >= N_NODESC) return;
        float a[NFEAT];
#pragma unroll
        for (int k = 0; k < NFEAT; k++)
            a[k] = __ldg(&agg[row * NFEAT + k]) + __ldg(&x[row * NFEAT + k]);
        float acc = bs[j];
#pragma unroll
        for (int k = 0; k < NFEAT; k++) acc = fmaf(a[k], Ws[k * HID + j], acc);
        out[(size_t)row * HID + j] = fmaxf(acc, 0.0f);
    }
}

// ================= layers 2,3: gather-aggregate, warp per node =============
__global__ void __launch_bounds__(256)
gather128(const float* __restrict__ hin, const int* __restrict__ srcs,
          const float* __restrict__ eas, const int* __restrict__ off,
          const float* __restrict__ We, const float* __restrict__ be,
          float* __restrict__ agg) {
    int n = (blockIdx.x * blockDim.x + threadIdx.x) >> 5;
    int lane = threadIdx.x & 31;
    if (n >= N_NODESC) return;
    float4 w = __ldg(&((const float4*)We)[lane]);
    float4 bb = __ldg(&((const float4*)be)[lane]);
    int i = __ldg(&off[n]);
    int end = __ldg(&off[n + 1]);
    const float4* h4 = (const float4*)hin;
    float4 acc = make_float4(0.f, 0.f, 0.f, 0.f);

    for (; i + 4 <= end; i += 4) {
        int s0 = __ldg(&srcs[i]);
        int s1 = __ldg(&srcs[i + 1]);
        int s2 = __ldg(&srcs[i + 2]);
        int s3 = __ldg(&srcs[i + 3]);
        float a0 = __ldg(&eas[i]);
        float a1 = __ldg(&eas[i + 1]);
        float a2 = __ldg(&eas[i + 2]);
        float a3 = __ldg(&eas[i + 3]);
        float4 v0 = h4[(size_t)s0 * (HID / 4) + lane];
        float4 v1 = h4[(size_t)s1 * (HID / 4) + lane];
        float4 v2 = h4[(size_t)s2 * (HID / 4) + lane];
        float4 v3 = h4[(size_t)s3 * (HID / 4) + lane];
        acc.x += fmaxf(fmaf(a0, w.x, bb.x) + v0.x, 0.f);
        acc.y += fmaxf(fmaf(a0, w.y, bb.y) + v0.y, 0.f);
        acc.z += fmaxf(fmaf(a0, w.z, bb.z) + v0.z, 0.f);
        acc.w += fmaxf(fmaf(a0, w.w, bb.w) + v0.w, 0.f);
        acc.x += fmaxf(fmaf(a1, w.x, bb.x) + v1.x, 0.f);
        acc.y += fmaxf(fmaf(a1, w.y, bb.y) + v1.y, 0.f);
        acc.z += fmaxf(fmaf(a1, w.z, bb.z) + v1.z, 0.f);
        acc.w += fmaxf(fmaf(a1, w.w, bb.w) + v1.w, 0.f);
        acc.x += fmaxf(fmaf(a2, w.x, bb.x) + v2.x, 0.f);
        acc.y += fmaxf(fmaf(a2, w.y, bb.y) + v2.y, 0.f);
        acc.z += fmaxf(fmaf(a2, w.z, bb.z) + v2.z, 0.f);
        acc.w += fmaxf(fmaf(a2, w.w, bb.w) + v2.w, 0.f);
        acc.x += fmaxf(fmaf(a3, w.x, bb.x) + v3.x, 0.f);
        acc.y += fmaxf(fmaf(a3, w.y, bb.y) + v3.y, 0.f);
        acc.z += fmaxf(fmaf(a3, w.z, bb.z) + v3.z, 0.f);
        acc.w += fmaxf(fmaf(a3, w.w, bb.w) + v3.w, 0.f);
    }
    for (; i < end; i++) {
        int s0 = __ldg(&srcs[i]);
        float a0 = __ldg(&eas[i]);
        float4 v0 = h4[(size_t)s0 * (HID / 4) + lane];
        acc.x += fmaxf(fmaf(a0, w.x, bb.x) + v0.x, 0.f);
        acc.y += fmaxf(fmaf(a0, w.y, bb.y) + v0.y, 0.f);
        acc.z += fmaxf(fmaf(a0, w.z, bb.z) + v0.z, 0.f);
        acc.w += fmaxf(fmaf(a0, w.w, bb.w) + v0.w, 0.f);
    }
    ((float4*)agg)[(size_t)n * (HID / 4) + lane] = acc;
}

// ====== layers 2,3 gemm: relu((agg + xin) @ W + b) via tf32 tensor cores ===
// BM=128, BN=128, K=128. 256 threads = 8 warps (4x2); each warp 32x64 C-tile.
// W pre-rounded to tf32 and staged once per block; A staged+rounded per tile.
#define TLD 132                      // padded row stride (floats)
#define GEMM_SMEM_TF ((HID * TLD + HID * TLD + HID) * 4)

__global__ void __launch_bounds__(256, 1)
gemm128_tf32(const float* __restrict__ agg, const float* __restrict__ xin,
             const float* __restrict__ W, const float* __restrict__ b,
             float* __restrict__ out) {
    extern __shared__ float smem[];
    float* Ws = smem;                 // [128][TLD], tf32-rounded
    float* As = smem + HID * TLD;     // [128][TLD]
    float* bs = As + HID * TLD;       // [128]

    int tid = threadIdx.x;
    int wid = tid >> 5;
    int warp_m = wid >> 1;            // 0..3 -> row block of 32
    int warp_n = wid & 1;             // 0..1 -> col block of 64

    // stage W once (tf32-rounded so fragments load without conversion)
    for (int i = tid; i < HID * (HID / 4); i += 256) {
        int r = i >> 5, q = i & 31;
        float4 v = ((const float4*)W)[i];
        v.x = wmma::__float_to_tf32(v.x);
        v.y = wmma::__float_to_tf32(v.y);
        v.z = wmma::__float_to_tf32(v.z);
        v.w = wmma::__float_to_tf32(v.w);
        *(float4*)&Ws[r * TLD + q * 4] = v;
    }
    if (tid < HID) bs[tid] = b[tid];
    __syncthreads();

    int ntiles = (N_NODESC + HID - 1) / HID;
    for (int tile = blockIdx.x; tile < ntiles; tile += gridDim.x) {
        int row0 = tile * HID;

        // stage A = tf32(agg + xin)
        for (int i = tid; i < HID * (HID / 4); i += 256) {
            int r = i >> 5, q = i & 31;
            int row = row0 + r;
            float4 v = make_float4(0.f, 0.f, 0.f, 0.f);
            if (row < N_NODESC) {
                float4 ag = ((const float4*)(agg + (size_t)row * HID))[q];
                float4 xx = ((const float4*)(xin + (size_t)row * HID))[q];
                v.x = wmma::__float_to_tf32(ag.x + xx.x);
                v.y = wmma::__float_to_tf32(ag.y + xx.y);
                v.z = wmma::__float_to_tf32(ag.z + xx.z);
                v.w = wmma::__float_to_tf32(ag.w + xx.w);
            }
            *(float4*)&As[r * TLD + q * 4] = v;
        }
        __syncthreads();

        wmma::fragment<wmma::accumulator, 16, 16, 8, float> acc[2][4];
#pragma unroll
        for (int mi = 0; mi < 2; mi++)
#pragma unroll
            for (int ni = 0; ni < 4; ni++)
                wmma::fill_fragment(acc[mi][ni], 0.0f);

#pragma unroll
        for (int k = 0; k < HID; k += 8) {
            wmma::fragment<wmma::matrix_a, 16, 16, 8, wmma::precision::tf32,
                           wmma::row_major> af[2];
#pragma unroll
            for (int mi = 0; mi < 2; mi++)
                wmma::load_matrix_sync(af[mi],
                    &As[(warp_m * 32 + mi * 16) * TLD + k], TLD);
#pragma unroll
            for (int ni = 0; ni < 4; ni++) {
                wmma::fragment<wmma::matrix_b, 16, 16, 8, wmma::precision::tf32,
                               wmma::row_major> bf;
                wmma::load_matrix_sync(bf,
                    &Ws[k * TLD + warp_n * 64 + ni * 16], TLD);
#pragma unroll
                for (int mi = 0; mi < 2; mi++)
                    wmma::mma_sync(acc[mi][ni], af[mi], bf, acc[mi][ni]);
            }
        }
        __syncthreads();

        // write accumulators to As, then epilogue: out = relu(acc + bias)
#pragma unroll
        for (int mi = 0; mi < 2; mi++)
#pragma unroll
            for (int ni = 0; ni < 4; ni++)
                wmma::store_matrix_sync(
                    &As[(warp_m * 32 + mi * 16) * TLD + warp_n * 64 + ni * 16],
                    acc[mi][ni], TLD, wmma::mem_row_major);
        __syncthreads();

        for (int i = tid; i < HID * (HID / 4); i += 256) {
            int r = i >> 5, q = i & 31;
            int row = row0 + r;
            if (row < N_NODESC) {
                float4 v = *(const float4*)&As[r * TLD + q * 4];
                float4 bv = *(const float4*)&bs[q * 4];
                float4 o;
                o.x = fmaxf(v.x + bv.x, 0.0f);
                o.y = fmaxf(v.y + bv.y, 0.0f);
                o.z = fmaxf(v.z + bv.z, 0.0f);
                o.w = fmaxf(v.w + bv.w, 0.0f);
                *(float4*)&out[(size_t)row * HID + q * 4] = o;
            }
        }
        __syncthreads();
    }
}

// ---------------- mean pool: segment sums over sorted batch ---------------
#define POOL_CHUNK 512
__global__ void pool_kernel(const float* __restrict__ h,
                            const int* __restrict__ batch,
                            float* __restrict__ pool,
                            float* __restrict__ cnt) {
    int j = threadIdx.x;  // 128
    int start = blockIdx.x * POOL_CHUNK;
    if (start >= N_NODESC) return;
    int end = start + POOL_CHUNK;
    if (end > N_NODESC) end = N_NODESC;
    int cur = __ldg(&batch[start]);
    float acc = 0.0f, c = 0.0f;
    for (int i = start; i < end; i++) {
        int bg = __ldg(&batch[i]);
        if (bg != cur) {
            atomicAdd(&pool[cur * HID + j], acc);
            if (j == 0) atomicAdd(&cnt[cur], c);
            acc = 0.0f; c = 0.0f; cur = bg;
        }
        acc += h[(size_t)i * HID + j];
        c += 1.0f;
    }
    atomicAdd(&pool[cur * HID + j], acc);
    if (j == 0) atomicAdd(&cnt[cur], c);
}

// ---------------- final: (pool/cnt) @ Wlin + blin, 8x5 out ----------------
__global__ void final_kernel(const float* __restrict__ pool,
                             const float* __restrict__ cnt,
                             const float* __restrict__ Wlin,
                             const float* __restrict__ blin,
                             float* __restrict__ out) {
    int t = threadIdx.x;
    if (t >= NGRAPHS * NCLASS) return;
    int g = t / NCLASS, c = t % NCLASS;
    float inv = 1.0f / fmaxf(cnt[g], 1.0f);
    float acc = blin[c];
#pragma unroll 8
    for (int k = 0; k < HID; k++)
        acc = fmaf(pool[g * HID + k] * inv, Wlin[k * NCLASS + c], acc);
    out[t] = acc;
}

// ---------------- launch ---------------------------------------------------
extern "C" void kernel_launch(void* const* d_in, const int* in_sizes, int n_in,
                              void* d_out, int out_size) {
    const float* x    = (const float*)d_in[0];
    const int*   ei   = (const int*)d_in[1];
    const float* ea   = (const float*)d_in[2];
    const int*   batch= (const int*)d_in[3];
    const float* We1  = (const float*)d_in[4];
    const float* be1  = (const float*)d_in[5];
    const float* W1   = (const float*)d_in[6];
    const float* b1   = (const float*)d_in[7];
    const float* We2  = (const float*)d_in[8];
    const float* be2  = (const float*)d_in[9];
    const float* W2   = (const float*)d_in[10];
    const float* b2   = (const float*)d_in[11];
    const float* We3  = (const float*)d_in[12];
    const float* be3  = (const float*)d_in[13];
    const float* W3   = (const float*)d_in[14];
    const float* b3   = (const float*)d_in[15];
    const float* Wlin = (const float*)d_in[16];
    const float* blin = (const float*)d_in[17];
    float* out = (float*)d_out;

    const int* src = ei;
    const int* dst = ei + N_EDGESC;

    float *agg, *h0, *h1, *pool, *cnt, *eas;
    int *deg, *off, *cur, *bsum, *perm, *srcs;
    cudaGetSymbolAddress((void**)&agg, g_agg);
    cudaGetSymbolAddress((void**)&h0, g_h0);
    cudaGetSymbolAddress((void**)&h1, g_h1);
    cudaGetSymbolAddress((void**)&pool, g_pool);
    cudaGetSymbolAddress((void**)&cnt, g_cnt);
    cudaGetSymbolAddress((void**)&deg, g_deg);
    cudaGetSymbolAddress((void**)&off, g_off);
    cudaGetSymbolAddress((void**)&cur, g_cur);
    cudaGetSymbolAddress((void**)&bsum, g_bsum);
    cudaGetSymbolAddress((void**)&perm, g_perm);
    cudaGetSymbolAddress((void**)&srcs, g_srcs);
    cudaGetSymbolAddress((void**)&eas, g_eas);

    cudaFuncSetAttribute(gemm128_tf32,
                         cudaFuncAttributeMaxDynamicSharedMemorySize,
                         GEMM_SMEM_TF);

    const int warp_blocks = (N_NODESC * 32 + 255) / 256;  // warp per node

    // ---- build CSR-by-destination + permuted edge data (reused 3x) ----
    cudaMemsetAsync(deg, 0, N_NODESC * sizeof(int));
    hist_kernel<<<(N_EDGESC + 255) / 256, 256>>>(dst, deg);
    scan_local<<<SCAN_NB, SCAN_T>>>(deg, off, bsum);
    scan_sums<<<1, 32>>>(bsum);
    scan_add<<<SCAN_NB, SCAN_T>>>(off, bsum);
    cudaMemcpyAsync(cur, off, N_NODESC * sizeof(int), cudaMemcpyDeviceToDevice);
    fill_kernel<<<(N_EDGESC + 255) / 256, 256>>>(dst, cur, perm);
    permute_edges<<<(N_EDGESC + 255) / 256, 256>>>(perm, src, ea, srcs, eas);

    // ---- layer 1 (in=7) ----
    gather7<<<warp_blocks, 256>>>(x, srcs, eas, off, We1, be1, agg);
    gemm7<<<(N_NODESC + GM1 - 1) / GM1, 128>>>(agg, x, W1, b1, h0);

    // ---- layer 2 ----
    gather128<<<warp_blocks, 256>>>(h0, srcs, eas, off, We2, be2, agg);
    gemm128_tf32<<<148, 256, GEMM_SMEM_TF>>>(agg, h0, W2, b2, h1);

    // ---- layer 3 ----
    gather128<<<warp_blocks, 256>>>(h1, srcs, eas, off, We3, be3, agg);
    gemm128_tf32<<<148, 256, GEMM_SMEM_TF>>>(agg, h1, W3, b3, h0);

    // ---- mean pool + classifier ----
    cudaMemsetAsync(pool, 0, NGRAPHS * HID * sizeof(float));
    cudaMemsetAsync(cnt, 0, NGRAPHS * sizeof(float));
    pool_kernel<<<(N_NODESC + POOL_CHUNK - 1) / POOL_CHUNK, 128>>>(h0, batch, pool, cnt);
    final_kernel<<<1, 64>>>(pool, cnt, Wlin, blin, out);
}

// round 13
// speedup vs baseline: 1.0283x; 1.0283x over previous
#include <cuda_runtime.h>
#include <cstddef>

#define N_NODESC 100000
#define N_EDGESC 1600000
#define NFEAT 7
#define HID 128
#define NCLASS 5
#define NGRAPHS 8

// ---------------- scratch (device globals; no allocation allowed) ----------
__device__ __align__(16) float g_agg[N_NODESC * NFEAT];   // layer-1 agg only
__device__ __align__(16) float g_h0[N_NODESC * HID];
__device__ __align__(16) float g_h1[N_NODESC * HID];
__device__ float g_pool[NGRAPHS * HID];
__device__ float g_cnt[NGRAPHS];
// CSR-by-destination scratch
__device__ int g_deg[N_NODESC];
__device__ int g_off[N_NODESC + 1];
__device__ int g_cur[N_NODESC];
__device__ int g_bsum[128];
// edge data directly scattered into CSR order
__device__ int g_srcs[N_EDGESC];
__device__ float g_eas[N_EDGESC];

// ================= CSR build ===============================================
__global__ void hist_kernel(const int* __restrict__ dst, int* __restrict__ deg) {
    int e = blockIdx.x * blockDim.x + threadIdx.x;
    if (e < N_EDGESC) atomicAdd(&deg[dst[e]], 1);
}

#define SCAN_T 256
#define SCAN_E 1024
#define SCAN_NB ((N_NODESC + SCAN_E - 1) / SCAN_E)   // 98

__global__ void scan_local(const int* __restrict__ deg, int* __restrict__ off,
                           int* __restrict__ bsum) {
    __shared__ int tsum[SCAN_T];
    int b = blockIdx.x, t = threadIdx.x;
    int base = b * SCAN_E + t * 4;
    int v[4], ex[4];
    int run = 0;
#pragma unroll
    for (int j = 0; j < 4; j++) {
        int idx = base + j;
        v[j] = (idx < N_NODESC) ? deg[idx] : 0;
        ex[j] = run;
        run += v[j];
    }
    tsum[t] = run;
    __syncthreads();
    for (int ofs = 1; ofs < SCAN_T; ofs <<= 1) {
        int val = (t >= ofs) ? tsum[t - ofs] : 0;
        __syncthreads();
        tsum[t] += val;
        __syncthreads();
    }
    int texc = tsum[t] - run;
#pragma unroll
    for (int j = 0; j < 4; j++) {
        int idx = base + j;
        if (idx < N_NODESC) off[idx] = texc + ex[j];
    }
    if (t == SCAN_T - 1) bsum[b] = tsum[t];
}

__global__ void scan_sums(int* __restrict__ bsum) {
    if (threadIdx.x == 0) {
        int run = 0;
        for (int b = 0; b < SCAN_NB; b++) {
            int t = bsum[b];
            bsum[b] = run;
            run += t;
        }
    }
}

__global__ void scan_add(int* __restrict__ off, const int* __restrict__ bsum) {
    int b = blockIdx.x, t = threadIdx.x;
    int add = bsum[b];
    int base = b * SCAN_E + t * 4;
#pragma unroll
    for (int j = 0; j < 4; j++) {
        int idx = base + j;
        if (idx < N_NODESC) off[idx] += add;
    }
    if (b == 0 && t == 0) off[N_NODESC] = N_EDGESC;
}

// fill srcs/eas directly in CSR order (no perm middleman)
__global__ void fill_kernel(const int* __restrict__ src,
                            const int* __restrict__ dst,
                            const float* __restrict__ ea,
                            int* __restrict__ cur,
                            int* __restrict__ srcs,
                            float* __restrict__ eas) {
    int e = blockIdx.x * blockDim.x + threadIdx.x;
    if (e < N_EDGESC) {
        int p = atomicAdd(&cur[dst[e]], 1);
        srcs[p] = src[e];
        eas[p] = ea[e];
    }
}

// ================= layer 1: in = 7, gather by destination ==================
__global__ void __launch_bounds__(256)
gather7(const float* __restrict__ x, const int* __restrict__ srcs,
        const float* __restrict__ eas, const int* __restrict__ off,
        const float* __restrict__ We, const float* __restrict__ be,
        float* __restrict__ agg7) {
    int n = (blockIdx.x * blockDim.x + threadIdx.x) >> 5;
    int lane = threadIdx.x & 31;
    if (n >= N_NODESC) return;
    float w[NFEAT], bb[NFEAT];
#pragma unroll
    for (int j = 0; j < NFEAT; j++) { w[j] = __ldg(&We[j]); bb[j] = __ldg(&be[j]); }
    int i0 = __ldg(&off[n]), i1 = __ldg(&off[n + 1]);
    float acc[NFEAT];
#pragma unroll
    for (int j = 0; j < NFEAT; j++) acc[j] = 0.0f;
    for (int i = i0 + lane; i < i1; i += 32) {
        int s = __ldg(&srcs[i]);
        float a = __ldg(&eas[i]);
#pragma unroll
        for (int j = 0; j < NFEAT; j++)
            acc[j] += fmaxf(fmaf(a, w[j], bb[j]) + __ldg(&x[s * NFEAT + j]), 0.0f);
    }
#pragma unroll
    for (int o = 16; o > 0; o >>= 1)
#pragma unroll
        for (int j = 0; j < NFEAT; j++)
            acc[j] += __shfl_down_sync(0xffffffffu, acc[j], o);
    if (lane == 0) {
#pragma unroll
        for (int j = 0; j < NFEAT; j++) agg7[n * NFEAT + j] = acc[j];
    }
}

// ---------------- layer 1 gemm: [N,7] @ [7,128], relu ---------------------
#define GM1 32
__global__ void gemm7(const float* __restrict__ agg, const float* __restrict__ x,
                      const float* __restrict__ W, const float* __restrict__ b,
                      float* __restrict__ out) {
    __shared__ float Ws[NFEAT * HID];
    __shared__ float bs[HID];
    int j = threadIdx.x;  // 128 threads
#pragma unroll
    for (int k = 0; k < NFEAT; k++) Ws[k * HID + j] = W[k * HID + j];
    bs[j] = b[j];
    __syncthreads();
    int row0 = blockIdx.x * GM1;
    for (int r = 0; r < GM1; r++) {
        int row = row0 + r;
        if (row >= N_NODESC) return;
        float a[NFEAT];
#pragma unroll
        for (int k = 0; k < NFEAT; k++)
            a[k] = __ldg(&agg[row * NFEAT + k]) + __ldg(&x[row * NFEAT + k]);
        float acc = bs[j];
#pragma unroll
        for (int k = 0; k < NFEAT; k++) acc = fmaf(a[k], Ws[k * HID + j], acc);
        out[(size_t)row * HID + j] = fmaxf(acc, 0.0f);
    }
}

// ====== layers 2,3 FUSED: gather (CSR) -> smem A-tile -> FFMA gemm ========
// Persistent blocks, 64-node tiles. Phase 1: each of 8 warps gathers 8 nodes
// (acc init = hin[n] row, so agg + x is free) into As. Phase 2: 8x4 register
// tile GEMM with W staged once per block. Cross-block phase interleave
// overlaps L2-bound gather with FFMA-bound gemm.
#define FBM 64
#define FUSED_SMEM ((HID * HID + FBM * HID + HID) * 4)   // 98816 B

__device__ __forceinline__ float4 gather_node(
    const float4* __restrict__ h4, const int* __restrict__ srcs,
    const float* __restrict__ eas, int i, int end, float4 w, float4 bb,
    int lane, float4 acc) {
    for (; i + 4 <= end; i += 4) {
        int s0 = __ldg(&srcs[i]);
        int s1 = __ldg(&srcs[i + 1]);
        int s2 = __ldg(&srcs[i + 2]);
        int s3 = __ldg(&srcs[i + 3]);
        float a0 = __ldg(&eas[i]);
        float a1 = __ldg(&eas[i + 1]);
        float a2 = __ldg(&eas[i + 2]);
        float a3 = __ldg(&eas[i + 3]);
        float4 v0 = h4[(size_t)s0 * (HID / 4) + lane];
        float4 v1 = h4[(size_t)s1 * (HID / 4) + lane];
        float4 v2 = h4[(size_t)s2 * (HID / 4) + lane];
        float4 v3 = h4[(size_t)s3 * (HID / 4) + lane];
        acc.x += fmaxf(fmaf(a0, w.x, bb.x) + v0.x, 0.f);
        acc.y += fmaxf(fmaf(a0, w.y, bb.y) + v0.y, 0.f);
        acc.z += fmaxf(fmaf(a0, w.z, bb.z) + v0.z, 0.f);
        acc.w += fmaxf(fmaf(a0, w.w, bb.w) + v0.w, 0.f);
        acc.x += fmaxf(fmaf(a1, w.x, bb.x) + v1.x, 0.f);
        acc.y += fmaxf(fmaf(a1, w.y, bb.y) + v1.y, 0.f);
        acc.z += fmaxf(fmaf(a1, w.z, bb.z) + v1.z, 0.f);
        acc.w += fmaxf(fmaf(a1, w.w, bb.w) + v1.w, 0.f);
        acc.x += fmaxf(fmaf(a2, w.x, bb.x) + v2.x, 0.f);
        acc.y += fmaxf(fmaf(a2, w.y, bb.y) + v2.y, 0.f);
        acc.z += fmaxf(fmaf(a2, w.z, bb.z) + v2.z, 0.f);
        acc.w += fmaxf(fmaf(a2, w.w, bb.w) + v2.w, 0.f);
        acc.x += fmaxf(fmaf(a3, w.x, bb.x) + v3.x, 0.f);
        acc.y += fmaxf(fmaf(a3, w.y, bb.y) + v3.y, 0.f);
        acc.z += fmaxf(fmaf(a3, w.z, bb.z) + v3.z, 0.f);
        acc.w += fmaxf(fmaf(a3, w.w, bb.w) + v3.w, 0.f);
    }
    for (; i < end; i++) {
        int s0 = __ldg(&srcs[i]);
        float a0 = __ldg(&eas[i]);
        float4 v0 = h4[(size_t)s0 * (HID / 4) + lane];
        acc.x += fmaxf(fmaf(a0, w.x, bb.x) + v0.x, 0.f);
        acc.y += fmaxf(fmaf(a0, w.y, bb.y) + v0.y, 0.f);
        acc.z += fmaxf(fmaf(a0, w.z, bb.z) + v0.z, 0.f);
        acc.w += fmaxf(fmaf(a0, w.w, bb.w) + v0.w, 0.f);
    }
    return acc;
}

__global__ void __launch_bounds__(256, 2)
gine_fused(const float* __restrict__ hin, const int* __restrict__ srcs,
           const float* __restrict__ eas, const int* __restrict__ off,
           const float* __restrict__ We, const float* __restrict__ be,
           const float* __restrict__ W, const float* __restrict__ b,
           float* __restrict__ out) {
    extern __shared__ float smem[];
    float* Ws = smem;                 // [128][128]
    float* As = smem + HID * HID;     // [64][128]
    float* bs = As + FBM * HID;       // [128]

    int tid = threadIdx.x;
    int wid = tid >> 5;
    int lane = tid & 31;

    // stage W + b once per block
    {
        const float4* Wg = (const float4*)W;
        float4* Ws4 = (float4*)Ws;
        for (int i = tid; i < HID * (HID / 4); i += 256) Ws4[i] = Wg[i];
        if (tid < HID) bs[tid] = b[tid];
    }

    float4 we = __ldg(&((const float4*)We)[lane]);
    float4 bb = __ldg(&((const float4*)be)[lane]);
    const float4* h4 = (const float4*)hin;

    int cg = tid & 31;
    int rg = tid >> 5;
    int j0 = cg * 4;
    int r0 = rg * 8;

    __syncthreads();

    int ntiles = (N_NODESC + FBM - 1) / FBM;
    for (int tile = blockIdx.x; tile < ntiles; tile += gridDim.x) {
        int row0 = tile * FBM;

        // ---- phase 1: gather 8 nodes per warp into As ----
#pragma unroll 1
        for (int q = 0; q < 8; q++) {
            int r = wid * 8 + q;
            int n = row0 + r;
            float4 acc = make_float4(0.f, 0.f, 0.f, 0.f);
            if (n < N_NODESC) {
                int i0 = __ldg(&off[n]);
                int i1 = __ldg(&off[n + 1]);
                acc = h4[(size_t)n * (HID / 4) + lane];   // (1+eps)*x, eps=0
                acc = gather_node(h4, srcs, eas, i0, i1, we, bb, lane, acc);
            }
            *(float4*)&As[r * HID + lane * 4] = acc;
        }
        __syncthreads();

        // ---- phase 2: gemm, relu, store ----
        float acc[8][4];
        {
            float4 bv = *(const float4*)&bs[j0];
#pragma unroll
            for (int i = 0; i < 8; i++) {
                acc[i][0] = bv.x; acc[i][1] = bv.y; acc[i][2] = bv.z; acc[i][3] = bv.w;
            }
        }

#pragma unroll 4
        for (int kk = 0; kk < HID; kk += 4) {
            float4 av[8];
#pragma unroll
            for (int i = 0; i < 8; i++)
                av[i] = *(const float4*)&As[(r0 + i) * HID + kk];
#pragma unroll
            for (int q = 0; q < 4; q++) {
                float4 wv = *(const float4*)&Ws[(kk + q) * HID + j0];
#pragma unroll
                for (int i = 0; i < 8; i++) {
                    float aval = (q == 0) ? av[i].x : (q == 1) ? av[i].y
                               : (q == 2) ? av[i].z : av[i].w;
                    acc[i][0] = fmaf(aval, wv.x, acc[i][0]);
                    acc[i][1] = fmaf(aval, wv.y, acc[i][1]);
                    acc[i][2] = fmaf(aval, wv.z, acc[i][2]);
                    acc[i][3] = fmaf(aval, wv.w, acc[i][3]);
                }
            }
        }

#pragma unroll
        for (int i = 0; i < 8; i++) {
            int row = row0 + r0 + i;
            if (row < N_NODESC) {
                float4 o;
                o.x = fmaxf(acc[i][0], 0.0f);
                o.y = fmaxf(acc[i][1], 0.0f);
                o.z = fmaxf(acc[i][2], 0.0f);
                o.w = fmaxf(acc[i][3], 0.0f);
                *(float4*)&out[(size_t)row * HID + j0] = o;
            }
        }
        __syncthreads();
    }
}

// ---------------- mean pool: segment sums over sorted batch ---------------
#define POOL_CHUNK 512
__global__ void pool_kernel(const float* __restrict__ h,
                            const int* __restrict__ batch,
                            float* __restrict__ pool,
                            float* __restrict__ cnt) {
    int j = threadIdx.x;  // 128
    int start = blockIdx.x * POOL_CHUNK;
    if (start >= N_NODESC) return;
    int end = start + POOL_CHUNK;
    if (end > N_NODESC) end = N_NODESC;
    int cur = __ldg(&batch[start]);
    float acc = 0.0f, c = 0.0f;
    for (int i = start; i < end; i++) {
        int bg = __ldg(&batch[i]);
        if (bg != cur) {
            atomicAdd(&pool[cur * HID + j], acc);
            if (j == 0) atomicAdd(&cnt[cur], c);
            acc = 0.0f; c = 0.0f; cur = bg;
        }
        acc += h[(size_t)i * HID + j];
        c += 1.0f;
    }
    atomicAdd(&pool[cur * HID + j], acc);
    if (j == 0) atomicAdd(&cnt[cur], c);
}

// ---------------- final: (pool/cnt) @ Wlin + blin, 8x5 out ----------------
__global__ void final_kernel(const float* __restrict__ pool,
                             const float* __restrict__ cnt,
                             const float* __restrict__ Wlin,
                             const float* __restrict__ blin,
                             float* __restrict__ out) {
    int t = threadIdx.x;
    if (t >= NGRAPHS * NCLASS) return;
    int g = t / NCLASS, c = t % NCLASS;
    float inv = 1.0f / fmaxf(cnt[g], 1.0f);
    float acc = blin[c];
#pragma unroll 8
    for (int k = 0; k < HID; k++)
        acc = fmaf(pool[g * HID + k] * inv, Wlin[k * NCLASS + c], acc);
    out[t] = acc;
}

// ---------------- launch ---------------------------------------------------
extern "C" void kernel_launch(void* const* d_in, const int* in_sizes, int n_in,
                              void* d_out, int out_size) {
    const float* x    = (const float*)d_in[0];
    const int*   ei   = (const int*)d_in[1];
    const float* ea   = (const float*)d_in[2];
    const int*   batch= (const int*)d_in[3];
    const float* We1  = (const float*)d_in[4];
    const float* be1  = (const float*)d_in[5];
    const float* W1   = (const float*)d_in[6];
    const float* b1   = (const float*)d_in[7];
    const float* We2  = (const float*)d_in[8];
    const float* be2  = (const float*)d_in[9];
    const float* W2   = (const float*)d_in[10];
    const float* b2   = (const float*)d_in[11];
    const float* We3  = (const float*)d_in[12];
    const float* be3  = (const float*)d_in[13];
    const float* W3   = (const float*)d_in[14];
    const float* b3   = (const float*)d_in[15];
    const float* Wlin = (const float*)d_in[16];
    const float* blin = (const float*)d_in[17];
    float* out = (float*)d_out;

    const int* src = ei;
    const int* dst = ei + N_EDGESC;

    float *agg, *h0, *h1, *pool, *cnt, *eas;
    int *deg, *off, *cur, *bsum, *srcs;
    cudaGetSymbolAddress((void**)&agg, g_agg);
    cudaGetSymbolAddress((void**)&h0, g_h0);
    cudaGetSymbolAddress((void**)&h1, g_h1);
    cudaGetSymbolAddress((void**)&pool, g_pool);
    cudaGetSymbolAddress((void**)&cnt, g_cnt);
    cudaGetSymbolAddress((void**)&deg, g_deg);
    cudaGetSymbolAddress((void**)&off, g_off);
    cudaGetSymbolAddress((void**)&cur, g_cur);
    cudaGetSymbolAddress((void**)&bsum, g_bsum);
    cudaGetSymbolAddress((void**)&srcs, g_srcs);
    cudaGetSymbolAddress((void**)&eas, g_eas);

    cudaFuncSetAttribute(gine_fused,
                         cudaFuncAttributeMaxDynamicSharedMemorySize,
                         FUSED_SMEM);

    const int warp_blocks = (N_NODESC * 32 + 255) / 256;  // warp per node

    // ---- build CSR-by-destination with direct srcs/eas scatter ----
    cudaMemsetAsync(deg, 0, N_NODESC * sizeof(int));
    hist_kernel<<<(N_EDGESC + 255) / 256, 256>>>(dst, deg);
    scan_local<<<SCAN_NB, SCAN_T>>>(deg, off, bsum);
    scan_sums<<<1, 32>>>(bsum);
    scan_add<<<SCAN_NB, SCAN_T>>>(off, bsum);
    cudaMemcpyAsync(cur, off, N_NODESC * sizeof(int), cudaMemcpyDeviceToDevice);
    fill_kernel<<<(N_EDGESC + 255) / 256, 256>>>(src, dst, ea, cur, srcs, eas);

    // ---- layer 1 (in=7) ----
    gather7<<<warp_blocks, 256>>>(x, srcs, eas, off, We1, be1, agg);
    gemm7<<<(N_NODESC + GM1 - 1) / GM1, 128>>>(agg, x, W1, b1, h0);

    // ---- layer 2 (fused gather+gemm) ----
    gine_fused<<<296, 256, FUSED_SMEM>>>(h0, srcs, eas, off, We2, be2, W2, b2, h1);

    // ---- layer 3 (fused gather+gemm) ----
    gine_fused<<<296, 256, FUSED_SMEM>>>(h1, srcs, eas, off, We3, be3, W3, b3, h0);

    // ---- mean pool + classifier ----
    cudaMemsetAsync(pool, 0, NGRAPHS * HID * sizeof(float));
    cudaMemsetAsync(cnt, 0, NGRAPHS * sizeof(float));
    pool_kernel<<<(N_NODESC + POOL_CHUNK - 1) / POOL_CHUNK, 128>>>(h0, batch, pool, cnt);
    final_kernel<<<1, 64>>>(pool, cnt, Wlin, blin, out);
}

// round 16
// speedup vs baseline: 1.1590x; 1.1272x over previous
#include <cuda_runtime.h>
#include <cuda_fp16.h>
#include <cstddef>

#define N_NODESC 100000
#define N_EDGESC 1600000
#define NFEAT 7
#define HID 128
#define NCLASS 5
#define NGRAPHS 8

// ---------------- scratch (device globals; no allocation allowed) ----------
__device__ __align__(16) float g_agg[N_NODESC * HID];
__device__ __align__(16) float g_h0[N_NODESC * HID];
__device__ __align__(16) float g_h1[N_NODESC * HID];
__device__ __align__(16) __half g_h0f16[N_NODESC * HID];
__device__ __align__(16) __half g_h1f16[N_NODESC * HID];
__device__ float g_pool[NGRAPHS * HID];
__device__ float g_cnt[NGRAPHS];
// CSR-by-destination scratch
__device__ int g_deg[N_NODESC];
__device__ int g_off[N_NODESC + 1];
__device__ int g_cur[N_NODESC];
__device__ int g_bsum[128];
// edge data directly scattered into CSR order
__device__ int g_srcs[N_EDGESC];
__device__ float g_eas[N_EDGESC];

// ================= CSR build ===============================================
__global__ void hist_kernel(const int* __restrict__ dst, int* __restrict__ deg) {
    int e = blockIdx.x * blockDim.x + threadIdx.x;
    if (e < N_EDGESC) atomicAdd(&deg[dst[e]], 1);
}

#define SCAN_T 256
#define SCAN_E 1024
#define SCAN_NB ((N_NODESC + SCAN_E - 1) / SCAN_E)   // 98

__global__ void scan_local(const int* __restrict__ deg, int* __restrict__ off,
                           int* __restrict__ bsum) {
    __shared__ int tsum[SCAN_T];
    int b = blockIdx.x, t = threadIdx.x;
    int base = b * SCAN_E + t * 4;
    int v[4], ex[4];
    int run = 0;
#pragma unroll
    for (int j = 0; j < 4; j++) {
        int idx = base + j;
        v[j] = (idx < N_NODESC) ? deg[idx] : 0;
        ex[j] = run;
        run += v[j];
    }
    tsum[t] = run;
    __syncthreads();
    for (int ofs = 1; ofs < SCAN_T; ofs <<= 1) {
        int val = (t >= ofs) ? tsum[t - ofs] : 0;
        __syncthreads();
        tsum[t] += val;
        __syncthreads();
    }
    int texc = tsum[t] - run;
#pragma unroll
    for (int j = 0; j < 4; j++) {
        int idx = base + j;
        if (idx < N_NODESC) off[idx] = texc + ex[j];
    }
    if (t == SCAN_T - 1) bsum[b] = tsum[t];
}

__global__ void scan_sums(int* __restrict__ bsum) {
    if (threadIdx.x == 0) {
        int run = 0;
        for (int b = 0; b < SCAN_NB; b++) {
            int t = bsum[b];
            bsum[b] = run;
            run += t;
        }
    }
}

__global__ void scan_add(int* __restrict__ off, const int* __restrict__ bsum) {
    int b = blockIdx.x, t = threadIdx.x;
    int add = bsum[b];
    int base = b * SCAN_E + t * 4;
#pragma unroll
    for (int j = 0; j < 4; j++) {
        int idx = base + j;
        if (idx < N_NODESC) off[idx] += add;
    }
    if (b == 0 && t == 0) off[N_NODESC] = N_EDGESC;
}

// fill srcs/eas directly in CSR order (no perm middleman)
__global__ void fill_kernel(const int* __restrict__ src,
                            const int* __restrict__ dst,
                            const float* __restrict__ ea,
                            int* __restrict__ cur,
                            int* __restrict__ srcs,
                            float* __restrict__ eas) {
    int e = blockIdx.x * blockDim.x + threadIdx.x;
    if (e < N_EDGESC) {
        int p = atomicAdd(&cur[dst[e]], 1);
        srcs[p] = src[e];
        eas[p] = ea[e];
    }
}

// ================= layer 1: in = 7, gather by destination ==================
__global__ void __launch_bounds__(256)
gather7(const float* __restrict__ x, const int* __restrict__ srcs,
        const float* __restrict__ eas, const int* __restrict__ off,
        const float* __restrict__ We, const float* __restrict__ be,
        float* __restrict__ agg7) {
    int n = (blockIdx.x * blockDim.x + threadIdx.x) >> 5;
    int lane = threadIdx.x & 31;
    if (n >= N_NODESC) return;
    float w[NFEAT], bb[NFEAT];
#pragma unroll
    for (int j = 0; j < NFEAT; j++) { w[j] = __ldg(&We[j]); bb[j] = __ldg(&be[j]); }
    int i0 = __ldg(&off[n]), i1 = __ldg(&off[n + 1]);
    float acc[NFEAT];
#pragma unroll
    for (int j = 0; j < NFEAT; j++) acc[j] = 0.0f;
    for (int i = i0 + lane; i < i1; i += 32) {
        int s = __ldg(&srcs[i]);
        float a = __ldg(&eas[i]);
#pragma unroll
        for (int j = 0; j < NFEAT; j++)
            acc[j] += fmaxf(fmaf(a, w[j], bb[j]) + __ldg(&x[s * NFEAT + j]), 0.0f);
    }
#pragma unroll
    for (int o = 16; o > 0; o >>= 1)
#pragma unroll
        for (int j = 0; j < NFEAT; j++)
            acc[j] += __shfl_down_sync(0xffffffffu, acc[j], o);
    if (lane == 0) {
#pragma unroll
        for (int j = 0; j < NFEAT; j++) agg7[n * NFEAT + j] = acc[j];
    }
}

// ------- layer 1 gemm: [N,7] @ [7,128], relu; writes fp32 + fp16 copies ----
#define GM1 32
__global__ void gemm7(const float* __restrict__ agg, const float* __restrict__ x,
                      const float* __restrict__ W, const float* __restrict__ b,
                      float* __restrict__ out, __half* __restrict__ out16) {
    __shared__ float Ws[NFEAT * HID];
    __shared__ float bs[HID];
    int j = threadIdx.x;  // 128 threads
#pragma unroll
    for (int k = 0; k < NFEAT; k++) Ws[k * HID + j] = W[k * HID + j];
    bs[j] = b[j];
    __syncthreads();
    int row0 = blockIdx.x * GM1;
    for (int r = 0; r < GM1; r++) {
        int row = row0 + r;
        if (row >= N_NODESC) return;
        float a[NFEAT];
#pragma unroll
        for (int k = 0; k < NFEAT; k++)
            a[k] = __ldg(&agg[row * NFEAT + k]) + __ldg(&x[row * NFEAT + k]);
        float acc = bs[j];
#pragma unroll
        for (int k = 0; k < NFEAT; k++) acc = fmaf(a[k], Ws[k * HID + j], acc);
        float o = fmaxf(acc, 0.0f);
        out[(size_t)row * HID + j] = o;
        out16[(size_t)row * HID + j] = __float2half_rn(o);
    }
}

// ===== layers 2,3: gather-aggregate from fp16 features, warp per node ======
// Reads 256B/row (fp16) instead of 512B: halves the dominant L2 traffic.
// Accumulation and output stay fp32.
__global__ void __launch_bounds__(256)
gather128h(const __half* __restrict__ hin, const int* __restrict__ srcs,
           const float* __restrict__ eas, const int* __restrict__ off,
           const float* __restrict__ We, const float* __restrict__ be,
           float* __restrict__ agg) {
    int n = (blockIdx.x * blockDim.x + threadIdx.x) >> 5;
    int lane = threadIdx.x & 31;
    if (n >= N_NODESC) return;
    float4 w = __ldg(&((const float4*)We)[lane]);
    float4 bb = __ldg(&((const float4*)be)[lane]);
    int i = __ldg(&off[n]);
    int end = __ldg(&off[n + 1]);
    const uint2* h2 = (const uint2*)hin;      // 4 halves per lane per row
    float4 acc = make_float4(0.f, 0.f, 0.f, 0.f);

    for (; i + 4 <= end; i += 4) {
        int s0 = __ldg(&srcs[i]);
        int s1 = __ldg(&srcs[i + 1]);
        int s2 = __ldg(&srcs[i + 2]);
        int s3 = __ldg(&srcs[i + 3]);
        float a0 = __ldg(&eas[i]);
        float a1 = __ldg(&eas[i + 1]);
        float a2 = __ldg(&eas[i + 2]);
        float a3 = __ldg(&eas[i + 3]);
        uint2 r0 = __ldg(&h2[(size_t)s0 * 32 + lane]);
        uint2 r1 = __ldg(&h2[(size_t)s1 * 32 + lane]);
        uint2 r2 = __ldg(&h2[(size_t)s2 * 32 + lane]);
        uint2 r3 = __ldg(&h2[(size_t)s3 * 32 + lane]);
        float2 v0a = __half22float2(*(const __half2*)&r0.x);
        float2 v0b = __half22float2(*(const __half2*)&r0.y);
        float2 v1a = __half22float2(*(const __half2*)&r1.x);
        float2 v1b = __half22float2(*(const __half2*)&r1.y);
        float2 v2a = __half22float2(*(const __half2*)&r2.x);
        float2 v2b = __half22float2(*(const __half2*)&r2.y);
        float2 v3a = __half22float2(*(const __half2*)&r3.x);
        float2 v3b = __half22float2(*(const __half2*)&r3.y);
        acc.x += fmaxf(fmaf(a0, w.x, bb.x) + v0a.x, 0.f);
        acc.y += fmaxf(fmaf(a0, w.y, bb.y) + v0a.y, 0.f);
        acc.z += fmaxf(fmaf(a0, w.z, bb.z) + v0b.x, 0.f);
        acc.w += fmaxf(fmaf(a0, w.w, bb.w) + v0b.y, 0.f);
        acc.x += fmaxf(fmaf(a1, w.x, bb.x) + v1a.x, 0.f);
        acc.y += fmaxf(fmaf(a1, w.y, bb.y) + v1a.y, 0.f);
        acc.z += fmaxf(fmaf(a1, w.z, bb.z) + v1b.x, 0.f);
        acc.w += fmaxf(fmaf(a1, w.w, bb.w) + v1b.y, 0.f);
        acc.x += fmaxf(fmaf(a2, w.x, bb.x) + v2a.x, 0.f);
        acc.y += fmaxf(fmaf(a2, w.y, bb.y) + v2a.y, 0.f);
        acc.z += fmaxf(fmaf(a2, w.z, bb.z) + v2b.x, 0.f);
        acc.w += fmaxf(fmaf(a2, w.w, bb.w) + v2b.y, 0.f);
        acc.x += fmaxf(fmaf(a3, w.x, bb.x) + v3a.x, 0.f);
        acc.y += fmaxf(fmaf(a3, w.y, bb.y) + v3a.y, 0.f);
        acc.z += fmaxf(fmaf(a3, w.z, bb.z) + v3b.x, 0.f);
        acc.w += fmaxf(fmaf(a3, w.w, bb.w) + v3b.y, 0.f);
    }
    for (; i < end; i++) {
        int s0 = __ldg(&srcs[i]);
        float a0 = __ldg(&eas[i]);
        uint2 r0 = __ldg(&h2[(size_t)s0 * 32 + lane]);
        float2 v0a = __half22float2(*(const __half2*)&r0.x);
        float2 v0b = __half22float2(*(const __half2*)&r0.y);
        acc.x += fmaxf(fmaf(a0, w.x, bb.x) + v0a.x, 0.f);
        acc.y += fmaxf(fmaf(a0, w.y, bb.y) + v0a.y, 0.f);
        acc.z += fmaxf(fmaf(a0, w.z, bb.z) + v0b.x, 0.f);
        acc.w += fmaxf(fmaf(a0, w.w, bb.w) + v0b.y, 0.f);
    }
    ((float4*)agg)[(size_t)n * (HID / 4) + lane] = acc;
}

// --- layers 2,3 gemm: relu((agg + xin) @ W + b); fp32 out + fp16 copy ------
#define BM 64
#define GEMM_SMEM ((HID * HID + BM * HID + HID) * 4)
__global__ void __launch_bounds__(256, 2)
gemm128(const float* __restrict__ agg, const float* __restrict__ xin,
        const float* __restrict__ W, const float* __restrict__ b,
        float* __restrict__ out, __half* __restrict__ out16) {
    extern __shared__ float smem[];
    float* Ws = smem;                 // [128][128]
    float* As = smem + HID * HID;     // [64][128]
    float* bs = As + BM * HID;        // [128]

    {
        const float4* Wg = (const float4*)W;
        float4* Ws4 = (float4*)Ws;
        for (int i = threadIdx.x; i < HID * (HID / 4); i += 256) Ws4[i] = Wg[i];
        if (threadIdx.x < HID) bs[threadIdx.x] = b[threadIdx.x];
    }
    __syncthreads();

    int cg = threadIdx.x & 31;
    int rg = threadIdx.x >> 5;
    int j0 = cg * 4;
    int r0 = rg * 8;

    int ntiles = (N_NODESC + BM - 1) / BM;
    for (int tile = blockIdx.x; tile < ntiles; tile += gridDim.x) {
        int row0 = tile * BM;
        {
            float4* As4 = (float4*)As;
            for (int i = threadIdx.x; i < BM * (HID / 4); i += 256) {
                int r = i >> 5;
                int kq = i & 31;
                int row = row0 + r;
                float4 v = make_float4(0.f, 0.f, 0.f, 0.f);
                if (row < N_NODESC) {
                    float4 ag = ((const float4*)(agg + (size_t)row * HID))[kq];
                    float4 xx = ((const float4*)(xin + (size_t)row * HID))[kq];
                    v = make_float4(ag.x + xx.x, ag.y + xx.y, ag.z + xx.z, ag.w + xx.w);
                }
                As4[i] = v;
            }
        }
        __syncthreads();

        float acc[8][4];
        {
            float4 bv = *(const float4*)&bs[j0];
#pragma unroll
            for (int i = 0; i < 8; i++) {
                acc[i][0] = bv.x; acc[i][1] = bv.y; acc[i][2] = bv.z; acc[i][3] = bv.w;
            }
        }

#pragma unroll 4
        for (int kk = 0; kk < HID; kk += 4) {
            float4 av[8];
#pragma unroll
            for (int i = 0; i < 8; i++)
                av[i] = *(const float4*)&As[(r0 + i) * HID + kk];
#pragma unroll
            for (int q = 0; q < 4; q++) {
                float4 wv = *(const float4*)&Ws[(kk + q) * HID + j0];
#pragma unroll
                for (int i = 0; i < 8; i++) {
                    float aval = (q == 0) ? av[i].x : (q == 1) ? av[i].y
                               : (q == 2) ? av[i].z : av[i].w;
                    acc[i][0] = fmaf(aval, wv.x, acc[i][0]);
                    acc[i][1] = fmaf(aval, wv.y, acc[i][1]);
                    acc[i][2] = fmaf(aval, wv.z, acc[i][2]);
                    acc[i][3] = fmaf(aval, wv.w, acc[i][3]);
                }
            }
        }

#pragma unroll
        for (int i = 0; i < 8; i++) {
            int row = row0 + r0 + i;
            if (row < N_NODESC) {
                float4 o;
                o.x = fmaxf(acc[i][0], 0.0f);
                o.y = fmaxf(acc[i][1], 0.0f);
                o.z = fmaxf(acc[i][2], 0.0f);
                o.w = fmaxf(acc[i][3], 0.0f);
                *(float4*)&out[(size_t)row * HID + j0] = o;
                __half2 p0 = __floats2half2_rn(o.x, o.y);
                __half2 p1 = __floats2half2_rn(o.z, o.w);
                uint2 packed;
                packed.x = *(const unsigned int*)&p0;
                packed.y = *(const unsigned int*)&p1;
                *(uint2*)&out16[(size_t)row * HID + j0] = packed;
            }
        }
        __syncthreads();
    }
}

// ---------------- mean pool: segment sums over sorted batch ---------------
#define POOL_CHUNK 512
__global__ void pool_kernel(const float* __restrict__ h,
                            const int* __restrict__ batch,
                            float* __restrict__ pool,
                            float* __restrict__ cnt) {
    int j = threadIdx.x;  // 128
    int start = blockIdx.x * POOL_CHUNK;
    if (start >= N_NODESC) return;
    int end = start + POOL_CHUNK;
    if (end > N_NODESC) end = N_NODESC;
    int cur = __ldg(&batch[start]);
    float acc = 0.0f, c = 0.0f;
    for (int i = start; i < end; i++) {
        int bg = __ldg(&batch[i]);
        if (bg != cur) {
            atomicAdd(&pool[cur * HID + j], acc);
            if (j == 0) atomicAdd(&cnt[cur], c);
            acc = 0.0f; c = 0.0f; cur = bg;
        }
        acc += h[(size_t)i * HID + j];
        c += 1.0f;
    }
    atomicAdd(&pool[cur * HID + j], acc);
    if (j == 0) atomicAdd(&cnt[cur], c);
}

// ---------------- final: (pool/cnt) @ Wlin + blin, 8x5 out ----------------
__global__ void final_kernel(const float* __restrict__ pool,
                             const float* __restrict__ cnt,
                             const float* __restrict__ Wlin,
                             const float* __restrict__ blin,
                             float* __restrict__ out) {
    int t = threadIdx.x;
    if (t >= NGRAPHS * NCLASS) return;
    int g = t / NCLASS, c = t % NCLASS;
    float inv = 1.0f / fmaxf(cnt[g], 1.0f);
    float acc = blin[c];
#pragma unroll 8
    for (int k = 0; k < HID; k++)
        acc = fmaf(pool[g * HID + k] * inv, Wlin[k * NCLASS + c], acc);
    out[t] = acc;
}

// ---------------- launch ---------------------------------------------------
extern "C" void kernel_launch(void* const* d_in, const int* in_sizes, int n_in,
                              void* d_out, int out_size) {
    const float* x    = (const float*)d_in[0];
    const int*   ei   = (const int*)d_in[1];
    const float* ea   = (const float*)d_in[2];
    const int*   batch= (const int*)d_in[3];
    const float* We1  = (const float*)d_in[4];
    const float* be1  = (const float*)d_in[5];
    const float* W1   = (const float*)d_in[6];
    const float* b1   = (const float*)d_in[7];
    const float* We2  = (const float*)d_in[8];
    const float* be2  = (const float*)d_in[9];
    const float* W2   = (const float*)d_in[10];
    const float* b2   = (const float*)d_in[11];
    const float* We3  = (const float*)d_in[12];
    const float* be3  = (const float*)d_in[13];
    const float* W3   = (const float*)d_in[14];
    const float* b3   = (const float*)d_in[15];
    const float* Wlin = (const float*)d_in[16];
    const float* blin = (const float*)d_in[17];
    float* out = (float*)d_out;

    const int* src = ei;
    const int* dst = ei + N_EDGESC;

    float *agg, *h0, *h1, *pool, *cnt, *eas;
    __half *h0f16, *h1f16;
    int *deg, *off, *cur, *bsum, *srcs;
    cudaGetSymbolAddress((void**)&agg, g_agg);
    cudaGetSymbolAddress((void**)&h0, g_h0);
    cudaGetSymbolAddress((void**)&h1, g_h1);
    cudaGetSymbolAddress((void**)&h0f16, g_h0f16);
    cudaGetSymbolAddress((void**)&h1f16, g_h1f16);
    cudaGetSymbolAddress((void**)&pool, g_pool);
    cudaGetSymbolAddress((void**)&cnt, g_cnt);
    cudaGetSymbolAddress((void**)&deg, g_deg);
    cudaGetSymbolAddress((void**)&off, g_off);
    cudaGetSymbolAddress((void**)&cur, g_cur);
    cudaGetSymbolAddress((void**)&bsum, g_bsum);
    cudaGetSymbolAddress((void**)&srcs, g_srcs);
    cudaGetSymbolAddress((void**)&eas, g_eas);

    cudaFuncSetAttribute(gemm128, cudaFuncAttributeMaxDynamicSharedMemorySize,
                         GEMM_SMEM);

    const int warp_blocks = (N_NODESC * 32 + 255) / 256;  // warp per node

    // ---- build CSR-by-destination with direct srcs/eas scatter ----
    cudaMemsetAsync(deg, 0, N_NODESC * sizeof(int));
    hist_kernel<<<(N_EDGESC + 255) / 256, 256>>>(dst, deg);
    scan_local<<<SCAN_NB, SCAN_T>>>(deg, off, bsum);
    scan_sums<<<1, 32>>>(bsum);
    scan_add<<<SCAN_NB, SCAN_T>>>(off, bsum);
    cudaMemcpyAsync(cur, off, N_NODESC * sizeof(int), cudaMemcpyDeviceToDevice);
    fill_kernel<<<(N_EDGESC + 255) / 256, 256>>>(src, dst, ea, cur, srcs, eas);

    // ---- layer 1 (in=7) ----
    gather7<<<warp_blocks, 256>>>(x, srcs, eas, off, We1, be1, agg);
    gemm7<<<(N_NODESC + GM1 - 1) / GM1, 128>>>(agg, x, W1, b1, h0, h0f16);

    // ---- layer 2 (fp16 gather -> fp32 gemm) ----
    gather128h<<<warp_blocks, 256>>>(h0f16, srcs, eas, off, We2, be2, agg);
    gemm128<<<296, 256, GEMM_SMEM>>>(agg, h0, W2, b2, h1, h1f16);

    // ---- layer 3 ----
    gather128h<<<warp_blocks, 256>>>(h1f16, srcs, eas, off, We3, be3, agg);
    gemm128<<<296, 256, GEMM_SMEM>>>(agg, h1, W3, b3, h0, h0f16);

    // ---- mean pool + classifier ----
    cudaMemsetAsync(pool, 0, NGRAPHS * HID * sizeof(float));
    cudaMemsetAsync(cnt, 0, NGRAPHS * sizeof(float));
    pool_kernel<<<(N_NODESC + POOL_CHUNK - 1) / POOL_CHUNK, 128>>>(h0, batch, pool, cnt);
    final_kernel<<<1, 64>>>(pool, cnt, Wlin, blin, out);
}